// round 1
// baseline (speedup 1.0000x reference)
#include <cuda_runtime.h>
#include <math.h>

#define FULLMASK 0xffffffffu

static constexpr int NL     = 2048;
static constexpr int NQ     = 16384;
static constexpr int NB     = 2;
static constexpr int H      = 64;     // hidden = CIN = 64
static constexpr int PH     = 256;
static constexpr int COUT   = 3;
static constexpr int KCAP   = 32;
static constexpr int CAP    = 192;    // radius-candidate buffer per warp
static constexpr int THREADS= 256;
static constexpr int WARPS  = 8;
static constexpr int NBLOCK = 296;

// ---- dynamic shared memory layout (float offsets) ----
static constexpr int OFF_COORD = 0;         // 4096  (2048 x float2)
static constexpr int OFF_WE0   = 4096;      // 256   [4][64]
static constexpr int OFF_BE0   = 4352;      // 64
static constexpr int OFF_WE1   = 4416;      // 4096  [64][64] row-major (j contiguous)
static constexpr int OFF_BE1   = 8512;      // 64
static constexpr int OFF_WE2   = 8576;      // 4096
static constexpr int OFF_BE2   = 12672;     // 64
static constexpr int OFF_WSW0  = 12736;     // 32    [2][16]
static constexpr int OFF_BSW0  = 12768;     // 16
static constexpr int OFF_WSW1  = 12784;     // 32    [16][2]
static constexpr int OFF_BSW1  = 12816;     // 2 (+2 pad)
static constexpr int OFF_WP0   = 12820;     // 16384 [64][256]
static constexpr int OFF_BP0   = 29204;     // 256
static constexpr int OFF_WP1   = 29460;     // 768   [256][3]
static constexpr int OFF_BP1   = 30228;     // 3 (+1 pad)
static constexpr int OFF_STAGE = 30232;     // 16384 = [64][256] per-thread activation columns
static constexpr int OFF_DEC   = 46616;     // 512 = 8 warps x 64
static constexpr int OFF_CAND  = 47128;     // 8 warps x 192 x u64 = 3072 floats
static constexpr int SMEM_FLOATS = 50200;
static constexpr int SMEM_BYTES  = SMEM_FLOATS * 4;   // 200800 B < 227KB

__device__ __forceinline__ float gelu_f(float x) {
    return 0.5f * x * (1.0f + erff(x * 0.7071067811865476f));
}

// acc[64] = bias + stage_column^T * W   (W row-major [64][64], broadcast reads)
__device__ __forceinline__ void matvec64(const float* __restrict__ Wsm,
                                         const float* __restrict__ bsm,
                                         const float* __restrict__ stage,
                                         int tid, float acc[64]) {
#pragma unroll
    for (int j = 0; j < 64; j++) acc[j] = bsm[j];
#pragma unroll 4
    for (int i = 0; i < 64; i++) {
        float hv = stage[i * THREADS + tid];
        const float4* wr = (const float4*)(Wsm + i * 64);
#pragma unroll
        for (int j4 = 0; j4 < 16; j4++) {
            float4 w = wr[j4];
            acc[4*j4+0] = fmaf(hv, w.x, acc[4*j4+0]);
            acc[4*j4+1] = fmaf(hv, w.y, acc[4*j4+1]);
            acc[4*j4+2] = fmaf(hv, w.z, acc[4*j4+2]);
            acc[4*j4+3] = fmaf(hv, w.w, acc[4*j4+3]);
        }
    }
}

__global__ void __launch_bounds__(THREADS, 1)
magno_kernel(const float* __restrict__ lat,  const float* __restrict__ rnd,
             const float* __restrict__ qry,
             const float* __restrict__ we0,  const float* __restrict__ be0,
             const float* __restrict__ we1,  const float* __restrict__ be1,
             const float* __restrict__ we2,  const float* __restrict__ be2,
             const float* __restrict__ wsw0, const float* __restrict__ bsw0,
             const float* __restrict__ wsw1, const float* __restrict__ bsw1,
             const float* __restrict__ wp0,  const float* __restrict__ bp0,
             const float* __restrict__ wp1,  const float* __restrict__ bp1,
             float* __restrict__ out)
{
    extern __shared__ float sm[];
    const int tid = threadIdx.x;

    // ---- load weights / coords to SMEM ----
    for (int t = tid; t < NL*2;  t += THREADS) sm[OFF_COORD+t] = lat[t];
    for (int t = tid; t < 4*H;   t += THREADS) sm[OFF_WE0+t]  = we0[t];
    for (int t = tid; t < H;     t += THREADS) sm[OFF_BE0+t]  = be0[t];
    for (int t = tid; t < H*H;   t += THREADS) sm[OFF_WE1+t]  = we1[t];
    for (int t = tid; t < H;     t += THREADS) sm[OFF_BE1+t]  = be1[t];
    for (int t = tid; t < H*H;   t += THREADS) sm[OFF_WE2+t]  = we2[t];
    for (int t = tid; t < H;     t += THREADS) sm[OFF_BE2+t]  = be2[t];
    if (tid < 32)                sm[OFF_WSW0+tid]    = wsw0[tid];
    if (tid < 16)                sm[OFF_BSW0+tid]    = bsw0[tid];
    if (tid >= 32 && tid < 64)   sm[OFF_WSW1+tid-32] = wsw1[tid-32];
    if (tid >= 64 && tid < 66)   sm[OFF_BSW1+tid-64] = bsw1[tid-64];
    for (int t = tid; t < H*PH;    t += THREADS) sm[OFF_WP0+t] = wp0[t];
    for (int t = tid; t < PH;      t += THREADS) sm[OFF_BP0+t] = bp0[t];
    for (int t = tid; t < PH*COUT; t += THREADS) sm[OFF_WP1+t] = wp1[t];
    if (tid < COUT)              sm[OFF_BP1+tid]     = bp1[tid];
    __syncthreads();

    const int warp = tid >> 5, lane = tid & 31;
    unsigned long long* cand = (unsigned long long*)(sm + OFF_CAND) + warp * CAP;
    float* stage  = sm + OFF_STAGE;
    float* decbuf = sm + OFF_DEC + warp * H;
    const float2* crd = (const float2*)(sm + OFF_COORD);

    const float R0SQ = (float)(0.055 * 0.055);
    const float R1SQ = (float)(0.11  * 0.11);
    const unsigned lt_mask = (1u << lane) - 1u;

    for (int q = blockIdx.x * WARPS + warp; q < NB * NQ; q += gridDim.x * WARPS) {
        const int  bix = q >> 14;
        const float qx = qry[2*q], qy = qry[2*q+1];

        // ---- per-query scale-mixing weights (redundant per lane) ----
        float s0 = sm[OFF_BSW1+0], s1 = sm[OFF_BSW1+1];
#pragma unroll
        for (int t = 0; t < 16; t++) {
            float z = sm[OFF_BSW0+t] + qx*sm[OFF_WSW0+t] + qy*sm[OFF_WSW0+16+t];
            z = fmaxf(z, 0.0f);
            s0 += z * sm[OFF_WSW1+2*t+0];
            s1 += z * sm[OFF_WSW1+2*t+1];
        }
        float mx = fmaxf(s0, s1);
        float e0 = expf(s0 - mx), e1 = expf(s1 - mx);
        float inv = 1.0f / (e0 + e1);
        float sw0v = e0 * inv, sw1v = e1 * inv;

        // ---- radius-filtered candidate collection (warp-aggregated) ----
        int cnt = 0;
        for (int l = lane; l < NL; l += 32) {
            float2 y = crd[l];
            float dx = qx - y.x, dy = qy - y.y;
            // match XLA's  round(dx*dx) + round(dy*dy)  (no FMA contraction)
            float d2 = __fadd_rn(__fmul_rn(dx, dx), __fmul_rn(dy, dy));
            bool pr = d2 <= R1SQ;
            unsigned m = __ballot_sync(FULLMASK, pr);
            if (pr) {
                int pos = cnt + __popc(m & lt_mask);
                if (pos < CAP)
                    cand[pos] = ((unsigned long long)__float_as_uint(d2) << 32) | (unsigned)l;
            }
            cnt += __popc(m);
        }
        if (cnt > CAP) cnt = CAP;
        __syncwarp();

        // ---- exact K=32 smallest (d2, idx) selection ----
        unsigned long long mykey = 0x7f7fffff00000000ull;  // d2 = FLT_MAX, idx = 0
        int nsel;
        if (cnt <= KCAP) {
            nsel = cnt;
            if (lane < cnt) mykey = cand[lane];
        } else {
            nsel = KCAP;
            for (int r = 0; r < KCAP; r++) {
                unsigned long long best = ~0ull;
                for (int p = lane; p < cnt; p += 32) {
                    unsigned long long v = cand[p];
                    if (v < best) best = v;
                }
#pragma unroll
                for (int off = 16; off > 0; off >>= 1) {
                    unsigned long long o = __shfl_xor_sync(FULLMASK, best, off);
                    if (o < best) best = o;
                }
                if (lane == r) mykey = best;
                for (int p = lane; p < cnt; p += 32)
                    if (cand[p] == best) cand[p] = ~0ull;
                __syncwarp();
            }
        }
        float seld2  = __uint_as_float((unsigned)(mykey >> 32));
        int   selidx = (int)(mykey & 0xffffffffu);
        if (lane >= nsel) { seld2 = 3.4e38f; selidx = 0; }

        // ---- fold both scales into one per-neighbor scalar ----
        bool v0 = (lane < nsel) && (seld2 <= R0SQ);
        int  c0 = __popc(__ballot_sync(FULLMASK, v0));
        float coeff = 0.0f;
        if (v0)          coeff += sw0v / (float)(c0   > 1 ? c0   : 1);
        if (lane < nsel) coeff += sw1v / (float)(nsel > 1 ? nsel : 1);

        // ---- edge MLP: lane = neighbor ----
        float2 yc = crd[selidx];
        {
            const float* w0 = sm + OFF_WE0;
            const float* b0 = sm + OFF_BE0;
            for (int j = 0; j < H; j++) {
                float t = b0[j] + yc.x*w0[j] + yc.y*w0[64+j] + qx*w0[128+j] + qy*w0[192+j];
                stage[j * THREADS + tid] = gelu_f(t);
            }
        }
        float acc[64];
        matvec64(sm + OFF_WE1, sm + OFF_BE1, stage, tid, acc);
#pragma unroll
        for (int j = 0; j < 64; j++) stage[j * THREADS + tid] = gelu_f(acc[j]);
        matvec64(sm + OFF_WE2, sm + OFF_BE2, stage, tid, acc);

        // ---- k(x,y)*f(y), weighted, warp-reduce over neighbors ----
        const float4* frow = (const float4*)(rnd + (size_t)(bix * NL + selidx) * H);
#pragma unroll
        for (int j4 = 0; j4 < 16; j4++) {
            float4 f4 = __ldg(frow + j4);
            acc[4*j4+0] *= f4.x * coeff;
            acc[4*j4+1] *= f4.y * coeff;
            acc[4*j4+2] *= f4.z * coeff;
            acc[4*j4+3] *= f4.w * coeff;
        }
#pragma unroll
        for (int j = 0; j < 64; j++) {
            float v = acc[j];
#pragma unroll
            for (int off = 16; off > 0; off >>= 1)
                v += __shfl_xor_sync(FULLMASK, v, off);
            acc[j] = v;
        }
        if (lane == 0) {
#pragma unroll
            for (int j = 0; j < 64; j++) decbuf[j] = acc[j];
        }
        __syncwarp();

        // ---- projection MLP: 64 -> 256 (gelu) -> 3 ----
        float hp[8];
#pragma unroll
        for (int jj = 0; jj < 8; jj++) hp[jj] = sm[OFF_BP0 + jj*32 + lane];
        for (int i = 0; i < 64; i++) {
            float dv = decbuf[i];
#pragma unroll
            for (int jj = 0; jj < 8; jj++)
                hp[jj] = fmaf(dv, sm[OFF_WP0 + i*PH + jj*32 + lane], hp[jj]);
        }
#pragma unroll
        for (int jj = 0; jj < 8; jj++) hp[jj] = gelu_f(hp[jj]);
#pragma unroll
        for (int c = 0; c < COUT; c++) {
            float pv = 0.0f;
#pragma unroll
            for (int jj = 0; jj < 8; jj++)
                pv = fmaf(hp[jj], sm[OFF_WP1 + (jj*32 + lane)*COUT + c], pv);
#pragma unroll
            for (int off = 16; off > 0; off >>= 1)
                pv += __shfl_xor_sync(FULLMASK, pv, off);
            if (lane == 0) out[q * COUT + c] = pv + sm[OFF_BP1 + c];
        }
        __syncwarp();
    }
}

extern "C" void kernel_launch(void* const* d_in, const int* in_sizes, int n_in,
                              void* d_out, int out_size) {
    const float* lat  = (const float*)d_in[0];
    const float* rnd  = (const float*)d_in[1];
    const float* qry  = (const float*)d_in[2];
    const float* we0  = (const float*)d_in[3];
    const float* be0  = (const float*)d_in[4];
    const float* we1  = (const float*)d_in[5];
    const float* be1  = (const float*)d_in[6];
    const float* we2  = (const float*)d_in[7];
    const float* be2  = (const float*)d_in[8];
    const float* wsw0 = (const float*)d_in[9];
    const float* bsw0 = (const float*)d_in[10];
    const float* wsw1 = (const float*)d_in[11];
    const float* bsw1 = (const float*)d_in[12];
    const float* wp0  = (const float*)d_in[13];
    const float* bp0  = (const float*)d_in[14];
    const float* wp1  = (const float*)d_in[15];
    const float* bp1  = (const float*)d_in[16];
    float* out = (float*)d_out;

    cudaFuncSetAttribute(magno_kernel, cudaFuncAttributeMaxDynamicSharedMemorySize, SMEM_BYTES);
    magno_kernel<<<NBLOCK, THREADS, SMEM_BYTES>>>(
        lat, rnd, qry, we0, be0, we1, be1, we2, be2,
        wsw0, bsw0, wsw1, bsw1, wp0, bp0, wp1, bp1, out);
}